// round 7
// baseline (speedup 1.0000x reference)
#include <cuda_runtime.h>
#include <stdint.h>

// Problem shape (fixed by the reference)
#define NT     4000
#define NS     16
#define NR     512
#define NSR    (NS * NR)            // 8192 columns
#define NCHUNK 50
#define TCHUNK (NT / NCHUNK)        // 80
#define CB_COLS 1024                // columns per block (float4 x 256 threads)
#define NCB    (NSR / CB_COLS)      // 8 column-blocks
#define WRITERS_PER_CB (NCHUNK * 2) // 100

// Scratch (device globals; zero-initialized at module load).
// g_part is fully rewritten every launch -> no init kernel needed.
// Counters are monotone across launches; "last arrival" detected via modulo,
// so they never need resetting (graph-replay deterministic).
__device__ unsigned long long g_part[2][NCHUNK][NSR];   // 6.55 MB, L2-resident
__device__ double             g_blocksum[NCB];
__device__ unsigned int       g_cnt[NCB];
__device__ unsigned int       g_done;

__global__ void __launch_bounds__(256, 6)
tt_fused_kernel(const float* __restrict__ x,
                const float* __restrict__ y,
                float* __restrict__ out) {
    const int cb    = blockIdx.x;                 // 0..7   column block
    const int chunk = blockIdx.y;                 // 0..49  time chunk
    const int z     = blockIdx.z;                 // 0 = x, 1 = y
    const int t0    = chunk * TCHUNK;
    const int col0  = cb * CB_COLS + threadIdx.x * 4;   // first of 4 columns

    // ---- Phase 1: chunk-local argmax of v^2, float4-wide coalesced stream.
    //      4 independent columns per thread; unroll 4 => 64 B/thread in flight.
    const float4* __restrict__ src = (const float4*)
        ((z == 0 ? x : y) + (size_t)t0 * NSR + cb * CB_COLS) + threadIdx.x;

    float b0 = -1.0f, b1 = -1.0f, b2 = -1.0f, b3 = -1.0f;
    int   i0 = t0,    i1 = t0,    i2 = t0,    i3 = t0;
#pragma unroll 4
    for (int i = 0; i < TCHUNK; i++) {
        float4 v = src[(size_t)i * (NSR / 4)];
        float a0 = v.x * v.x, a1 = v.y * v.y, a2 = v.z * v.z, a3 = v.w * v.w;
        const int t = t0 + i;
        if (a0 > b0) { b0 = a0; i0 = t; }   // strict '>' => first max
        if (a1 > b1) { b1 = a1; i1 = t; }
        if (a2 > b2) { b2 = a2; i2 = t; }
        if (a3 > b3) { b3 = a3; i3 = t; }
    }
    // pack: (float_bits(v^2) << 32) | (NT-1-t). v^2 >= 0 so bits are order-
    // monotone; larger NT-1-t == smaller t wins ties -> argmax-first semantics.
    unsigned long long* __restrict__ dst = &g_part[z][chunk][col0];
    dst[0] = ((unsigned long long)__float_as_uint(b0) << 32) | (unsigned int)(NT - 1 - i0);
    dst[1] = ((unsigned long long)__float_as_uint(b1) << 32) | (unsigned int)(NT - 1 - i1);
    dst[2] = ((unsigned long long)__float_as_uint(b2) << 32) | (unsigned int)(NT - 1 - i2);
    dst[3] = ((unsigned long long)__float_as_uint(b3) << 32) | (unsigned int)(NT - 1 - i3);

    // ---- Phase 2: last of 100 writer-blocks for this cb reduces it ----
    __shared__ unsigned int s_old;
    __syncthreads();
    if (threadIdx.x == 0) {
        __threadfence();                          // publish g_part stores
        s_old = atomicAdd(&g_cnt[cb], 1u);
    }
    __syncthreads();
    if (s_old % WRITERS_PER_CB != WRITERS_PER_CB - 1) return;

    // This block is the per-column-block reducer (one per cb, 8 total).
    unsigned long long bx[4] = {0ull, 0ull, 0ull, 0ull};
    unsigned long long by[4] = {0ull, 0ull, 0ull, 0ull};
#pragma unroll 4
    for (int k = 0; k < NCHUNK; k++) {
#pragma unroll
        for (int j = 0; j < 4; j++) {
            unsigned long long px = g_part[0][k][col0 + j];
            unsigned long long py = g_part[1][k][col0 + j];
            bx[j] = (px > bx[j]) ? px : bx[j];
            by[j] = (py > by[j]) ? py : by[j];
        }
    }
    double v = 0.0;
#pragma unroll
    for (int j = 0; j < 4; j++) {
        // (NT-1-tx) - (NT-1-ty) = ty - tx; square is sign-invariant.
        const float d = (float)((int)(unsigned int)(by[j] & 0xffffffffull)
                              - (int)(unsigned int)(bx[j] & 0xffffffffull));
        v += (double)d * (double)d;
    }

    // block-reduce 256 doubles
    __shared__ double ssum[8];
    const int lane = threadIdx.x & 31;
    const int wid  = threadIdx.x >> 5;
#pragma unroll
    for (int off = 16; off > 0; off >>= 1)
        v += __shfl_down_sync(0xffffffffu, v, off);
    if (lane == 0) ssum[wid] = v;
    __syncthreads();

    __shared__ unsigned int s_old2;
    if (threadIdx.x == 0) {
        double w = 0.0;
#pragma unroll
        for (int i = 0; i < 8; i++) w += ssum[i];
        g_blocksum[cb] = w;
        __threadfence();                          // publish g_blocksum
        s_old2 = atomicAdd(&g_done, 1u);
    }
    __syncthreads();
    if (threadIdx.x != 0) return;
    if (s_old2 % NCB != NCB - 1) return;

    // ---- Phase 3: final arrival sums 8 partials, writes scalar MSE ----
    double s = 0.0;
#pragma unroll
    for (int i = 0; i < NCB; i++) s += g_blocksum[i];
    out[0] = (float)(s * (1.0 / (double)NSR));
}

extern "C" void kernel_launch(void* const* d_in, const int* in_sizes, int n_in,
                              void* d_out, int out_size) {
    const float* x = (const float*)d_in[0];
    const float* y = (const float*)d_in[1];
    float* out = (float*)d_out;
    (void)in_sizes; (void)n_in; (void)out_size;

    dim3 grid(NCB, NCHUNK, 2);
    tt_fused_kernel<<<grid, 256>>>(x, y, out);
}